// round 6
// baseline (speedup 1.0000x reference)
#include <cuda_runtime.h>

// StackMemory degenerate form:
//   out[0, t, 0, h] = softmax(x_t @ W^T + b)[0] * sigmoid(x_t @ D)   (all h)
//   out[0, t, d, h] = 0   for d >= 1
//
// R5 experiment: move the bulk zero-fill off the SM store path.
//   node 1: cudaMemsetAsync(d_out, 0, 419 MB)  -- driver fill engine
//   node 2: value kernel overwrites only the 8192 d=0 rows (13 MB)
// Tests whether the memset fill path beats the ~6.0 TB/s STG ceiling
// observed across R2-R4.

#define T_LEN 8192
#define HID   400
#define DEPTH 32
#define NTHREADS 256
#define ROWVEC (HID / 4)           // 100 float4 per (t, d) row
#define TVEC  (DEPTH * HID / 4)    // 3200 float4 per t

__global__ __launch_bounds__(NTHREADS)
void stackmem_value_kernel(const float4* __restrict__ x4,  // (T, 100)
                           const float4* __restrict__ W4,  // (3, 100)
                           const float*  __restrict__ b,   // (3,)
                           const float4* __restrict__ D4,  // (100,)
                           float4* __restrict__ out4)      // (T, 32, 100)
{
    // 1 warp per timestep, 8 timesteps per block.
    const int warp = threadIdx.x >> 5;
    const int lane = threadIdx.x & 31;
    const int t = blockIdx.x * 8 + warp;

    const float4* xt = x4 + (size_t)t * ROWVEC;

    float s0 = 0.f, s1 = 0.f, s2 = 0.f, sd = 0.f;
    #pragma unroll
    for (int base = 0; base < ROWVEC; base += 32) {
        int i = base + lane;
        if (i < ROWVEC) {
            float4 xv = xt[i];
            float4 w0 = W4[i];
            float4 w1 = W4[ROWVEC + i];
            float4 w2 = W4[2 * ROWVEC + i];
            float4 dv = D4[i];
            s0 = fmaf(xv.x, w0.x, fmaf(xv.y, w0.y, fmaf(xv.z, w0.z, fmaf(xv.w, w0.w, s0))));
            s1 = fmaf(xv.x, w1.x, fmaf(xv.y, w1.y, fmaf(xv.z, w1.z, fmaf(xv.w, w1.w, s1))));
            s2 = fmaf(xv.x, w2.x, fmaf(xv.y, w2.y, fmaf(xv.z, w2.z, fmaf(xv.w, w2.w, s2))));
            sd = fmaf(xv.x, dv.x, fmaf(xv.y, dv.y, fmaf(xv.z, dv.z, fmaf(xv.w, dv.w, sd))));
        }
    }

    #pragma unroll
    for (int off = 16; off > 0; off >>= 1) {
        s0 += __shfl_down_sync(0xffffffffu, s0, off);
        s1 += __shfl_down_sync(0xffffffffu, s1, off);
        s2 += __shfl_down_sync(0xffffffffu, s2, off);
        sd += __shfl_down_sync(0xffffffffu, sd, off);
    }

    float val;
    if (lane == 0) {
        float l0 = s0 + b[0];
        float l1 = s1 + b[1];
        float l2 = s2 + b[2];
        float m  = fmaxf(l0, fmaxf(l1, l2));
        float e0 = __expf(l0 - m);
        float e1 = __expf(l1 - m);
        float e2 = __expf(l2 - m);
        float push = e0 / (e0 + e1 + e2);
        float pv   = 1.0f / (1.0f + __expf(-sd));
        val = push * pv;
    }
    val = __shfl_sync(0xffffffffu, val, 0);

    const float4 v4 = make_float4(val, val, val, val);
    float4* o = out4 + (size_t)t * TVEC;    // d=0 row
    #pragma unroll
    for (int base = 0; base < ROWVEC; base += 32) {
        int i = base + lane;
        if (i < ROWVEC) __stcs(o + i, v4);
    }
}

extern "C" void kernel_launch(void* const* d_in, const int* in_sizes, int n_in,
                              void* d_out, int out_size) {
    const float4* x = (const float4*)d_in[0];  // hidden_state (1, 8192, 400)
    const float4* W = (const float4*)d_in[1];  // W_ap (3, 400)
    const float*  b = (const float*) d_in[2];  // b_ap (3,)
    const float4* D = (const float4*)d_in[3];  // D (1, 400)
    float4* out = (float4*)d_out;              // (1, 8192, 32, 400)

    // Bulk zero-fill via the driver fill path (graph memset node).
    cudaMemsetAsync(d_out, 0, (size_t)out_size * sizeof(float));

    // Overwrite the 8192 d=0 rows with the computed scalar.
    stackmem_value_kernel<<<T_LEN / 8, NTHREADS>>>(x, W, b, D, out);
}

// round 7
// speedup vs baseline: 1.0018x; 1.0018x over previous
#include <cuda_runtime.h>

// StackMemory degenerate form:
//   out[0, t, 0, h] = softmax(x_t @ W^T + b)[0] * sigmoid(x_t @ D)   (all h)
//   out[0, t, d, h] = 0   for d >= 1
//
// R6: hybrid CE + SM fill. R5 showed the memset (copy-engine) path sustains
// ~7.2 TB/s vs the ~6.0 TB/s SM STG ceiling, but serialized. Here we FORK the
// captured graph:
//   branch CE : memset of t in [0, TCE)        (~226 MB, no SM involvement)
//   branch SM : R2-style kernel for t in [TCE, 8192) (zeros + value rows)
//               + scalar-compute blocks stashing t<TCE scalars in scratch
//   join      : tiny pure-store tail writes t<TCE d=0 rows from scratch
// Both engines drain into DRAM concurrently.

#define T_LEN 8192
#define HID   400
#define DEPTH 32
#define NTHREADS 256
#define TCE   4608                  // timesteps zeroed by the copy engine
#define TSM   (T_LEN - TCE)         // 3584 timesteps handled by SM kernel
#define NVB   (TSM / 8)             // 448 value blocks
#define NZB   TSM                   // 3584 zero blocks
#define NSB   (TCE / 8)             // 576 scalar blocks
#define ROWVEC (HID / 4)            // 100 float4 per (t, d) row
#define TVEC  (DEPTH * HID / 4)     // 3200 float4 per t

__device__ float g_scalar[T_LEN];

// Warp-cooperative scalar: softmax(x_t W^T + b)[0] * sigmoid(x_t . D)
__device__ __forceinline__ float compute_val(const float4* __restrict__ x4,
                                             const float4* __restrict__ W4,
                                             const float*  __restrict__ b,
                                             const float4* __restrict__ D4,
                                             int t, int lane)
{
    const float4* xt = x4 + (size_t)t * ROWVEC;
    float s0 = 0.f, s1 = 0.f, s2 = 0.f, sd = 0.f;
    #pragma unroll
    for (int base = 0; base < ROWVEC; base += 32) {
        int i = base + lane;
        if (i < ROWVEC) {
            float4 xv = xt[i];
            float4 w0 = W4[i];
            float4 w1 = W4[ROWVEC + i];
            float4 w2 = W4[2 * ROWVEC + i];
            float4 dv = D4[i];
            s0 = fmaf(xv.x, w0.x, fmaf(xv.y, w0.y, fmaf(xv.z, w0.z, fmaf(xv.w, w0.w, s0))));
            s1 = fmaf(xv.x, w1.x, fmaf(xv.y, w1.y, fmaf(xv.z, w1.z, fmaf(xv.w, w1.w, s1))));
            s2 = fmaf(xv.x, w2.x, fmaf(xv.y, w2.y, fmaf(xv.z, w2.z, fmaf(xv.w, w2.w, s2))));
            sd = fmaf(xv.x, dv.x, fmaf(xv.y, dv.y, fmaf(xv.z, dv.z, fmaf(xv.w, dv.w, sd))));
        }
    }
    #pragma unroll
    for (int off = 16; off > 0; off >>= 1) {
        s0 += __shfl_down_sync(0xffffffffu, s0, off);
        s1 += __shfl_down_sync(0xffffffffu, s1, off);
        s2 += __shfl_down_sync(0xffffffffu, s2, off);
        sd += __shfl_down_sync(0xffffffffu, sd, off);
    }
    float val = 0.f;
    if (lane == 0) {
        float l0 = s0 + b[0];
        float l1 = s1 + b[1];
        float l2 = s2 + b[2];
        float m  = fmaxf(l0, fmaxf(l1, l2));
        float e0 = __expf(l0 - m);
        float e1 = __expf(l1 - m);
        float e2 = __expf(l2 - m);
        float push = e0 / (e0 + e1 + e2);
        float pv   = 1.0f / (1.0f + __expf(-sd));
        val = push * pv;
    }
    return __shfl_sync(0xffffffffu, val, 0);
}

__global__ __launch_bounds__(NTHREADS)
void stackmem_main_kernel(const float4* __restrict__ x4,
                          const float4* __restrict__ W4,
                          const float*  __restrict__ b,
                          const float4* __restrict__ D4,
                          float4* __restrict__ out4)
{
    const int bid = blockIdx.x;
    const int tid = threadIdx.x;
    const int warp = tid >> 5;
    const int lane = tid & 31;

    if (bid < NVB) {
        // ---- value block: t in [TCE, 8192), compute + write d=0 row -----
        const int t = TCE + bid * 8 + warp;
        float val = compute_val(x4, W4, b, D4, t, lane);
        const float4 v4 = make_float4(val, val, val, val);
        float4* o = out4 + (size_t)t * TVEC;
        #pragma unroll
        for (int base = 0; base < ROWVEC; base += 32) {
            int i = base + lane;
            if (i < ROWVEC) __stcs(o + i, v4);
        }
    } else if (bid < NVB + NZB) {
        // ---- zero block: one t in [TCE, 8192), d>=1 region --------------
        const int t = TCE + (bid - NVB);
        float4* o = out4 + (size_t)t * TVEC + ROWVEC;
        const float4 z = make_float4(0.f, 0.f, 0.f, 0.f);
        const int N = TVEC - ROWVEC;   // 3100
        #pragma unroll 4
        for (int i = tid; i < N; i += NTHREADS) {
            __stcs(o + i, z);
        }
    } else {
        // ---- scalar block: t in [0, TCE), stash scalar in scratch -------
        const int t = (bid - NVB - NZB) * 8 + warp;
        float val = compute_val(x4, W4, b, D4, t, lane);
        if (lane == 0) g_scalar[t] = val;
    }
}

__global__ __launch_bounds__(NTHREADS)
void stackmem_tail_kernel(float4* __restrict__ out4)
{
    // Pure stores: d=0 rows for t in [0, TCE) from precomputed scalars.
    const int warp = threadIdx.x >> 5;
    const int lane = threadIdx.x & 31;
    const int t = blockIdx.x * 8 + warp;
    const float val = g_scalar[t];
    const float4 v4 = make_float4(val, val, val, val);
    float4* o = out4 + (size_t)t * TVEC;
    #pragma unroll
    for (int base = 0; base < ROWVEC; base += 32) {
        int i = base + lane;
        if (i < ROWVEC) __stcs(o + i, v4);
    }
}

extern "C" void kernel_launch(void* const* d_in, const int* in_sizes, int n_in,
                              void* d_out, int out_size) {
    const float4* x = (const float4*)d_in[0];  // hidden_state (1, 8192, 400)
    const float4* W = (const float4*)d_in[1];  // W_ap (3, 400)
    const float*  b = (const float*) d_in[2];  // b_ap (3,)
    const float4* D = (const float4*)d_in[3];  // D (1, 400)
    float4* out = (float4*)d_out;              // (1, 8192, 32, 400)

    static cudaStream_t s1 = nullptr;
    static cudaEvent_t ev_fork = nullptr, ev_ce = nullptr;
    if (s1 == nullptr) {
        cudaStreamCreateWithFlags(&s1, cudaStreamNonBlocking);
        cudaEventCreateWithFlags(&ev_fork, cudaEventDisableTiming);
        cudaEventCreateWithFlags(&ev_ce, cudaEventDisableTiming);
    }

    // Fork: copy-engine memset of t < TCE on side stream.
    cudaEventRecord(ev_fork, 0);
    cudaStreamWaitEvent(s1, ev_fork, 0);
    cudaMemsetAsync(d_out, 0, (size_t)TCE * DEPTH * HID * sizeof(float), s1);
    cudaEventRecord(ev_ce, s1);

    // SM branch: zeros + values for t >= TCE, plus scalar precompute.
    stackmem_main_kernel<<<NVB + NZB + NSB, NTHREADS>>>(x, W, b, D, out);

    // Join, then overwrite the memset region's d=0 rows.
    cudaStreamWaitEvent(0, ev_ce, 0);
    stackmem_tail_kernel<<<TCE / 8, NTHREADS>>>(out);
}

// round 8
// speedup vs baseline: 1.0625x; 1.0605x over previous
#include <cuda_runtime.h>

// StackMemory degenerate form:
//   out[0, t, 0, h] = softmax(x_t @ W^T + b)[0] * sigmoid(x_t @ D)   (all h)
//   out[0, t, d, h] = 0   for d >= 1
// Store-bandwidth bound. Exact R2-winning block-level role split:
//   blocks [0, NVBLK)          : value blocks, 1 warp per timestep (8 t / block)
//   blocks [NVBLK, NVBLK+T_LEN): zero blocks, one t each, streaming STG.128
// R7 change: zero stores use DEFAULT cache policy (no .cs). Theory: eager
// .cs eviction drains L2 in issue order; default policy batches contiguous
// dirty spans for better DRAM page locality (driver memset achieves 7.2 TB/s
// vs our 6.0 with .cs).

#define T_LEN 8192
#define HID   400
#define DEPTH 32
#define NTHREADS 256
#define NVBLK (T_LEN / 8)          // 1024 value blocks, 8 warps each
#define ROWVEC (HID / 4)           // 100 float4 per (t, d) row
#define TVEC  (DEPTH * HID / 4)    // 3200 float4 per t

__global__ __launch_bounds__(NTHREADS)
void stackmem_kernel(const float4* __restrict__ x4,  // (T, 100)
                     const float4* __restrict__ W4,  // (3, 100)
                     const float*  __restrict__ b,   // (3,)
                     const float4* __restrict__ D4,  // (100,)
                     float4* __restrict__ out4)      // (T, 32, 100)
{
    const int bid = blockIdx.x;
    const int tid = threadIdx.x;

    if (bid >= NVBLK) {
        // ================= zero block: one timestep's d>=1 region ========
        const int t = bid - NVBLK;
        float4* o = out4 + (size_t)t * TVEC + ROWVEC;   // skip d=0 row
        const float4 z = make_float4(0.f, 0.f, 0.f, 0.f);
        const int N = TVEC - ROWVEC;                    // 3100
        #pragma unroll 4
        for (int i = tid; i < N; i += NTHREADS) {
            o[i] = z;                                   // plain STG.128
        }
        return;
    }

    // ==================== value block: 1 warp per t ======================
    const int warp = tid >> 5;
    const int lane = tid & 31;
    const int t = bid * 8 + warp;

    const float4* xt = x4 + (size_t)t * ROWVEC;

    float s0 = 0.f, s1 = 0.f, s2 = 0.f, sd = 0.f;
    #pragma unroll
    for (int base = 0; base < ROWVEC; base += 32) {
        int i = base + lane;
        if (i < ROWVEC) {
            float4 xv = xt[i];
            float4 w0 = W4[i];
            float4 w1 = W4[ROWVEC + i];
            float4 w2 = W4[2 * ROWVEC + i];
            float4 dv = D4[i];
            s0 = fmaf(xv.x, w0.x, fmaf(xv.y, w0.y, fmaf(xv.z, w0.z, fmaf(xv.w, w0.w, s0))));
            s1 = fmaf(xv.x, w1.x, fmaf(xv.y, w1.y, fmaf(xv.z, w1.z, fmaf(xv.w, w1.w, s1))));
            s2 = fmaf(xv.x, w2.x, fmaf(xv.y, w2.y, fmaf(xv.z, w2.z, fmaf(xv.w, w2.w, s2))));
            sd = fmaf(xv.x, dv.x, fmaf(xv.y, dv.y, fmaf(xv.z, dv.z, fmaf(xv.w, dv.w, sd))));
        }
    }

    #pragma unroll
    for (int off = 16; off > 0; off >>= 1) {
        s0 += __shfl_down_sync(0xffffffffu, s0, off);
        s1 += __shfl_down_sync(0xffffffffu, s1, off);
        s2 += __shfl_down_sync(0xffffffffu, s2, off);
        sd += __shfl_down_sync(0xffffffffu, sd, off);
    }

    float val;
    if (lane == 0) {
        float l0 = s0 + b[0];
        float l1 = s1 + b[1];
        float l2 = s2 + b[2];
        float m  = fmaxf(l0, fmaxf(l1, l2));
        float e0 = __expf(l0 - m);
        float e1 = __expf(l1 - m);
        float e2 = __expf(l2 - m);
        float push = e0 / (e0 + e1 + e2);
        float pv   = 1.0f / (1.0f + __expf(-sd));
        val = push * pv;
    }
    val = __shfl_sync(0xffffffffu, val, 0);

    const float4 v4 = make_float4(val, val, val, val);
    float4* o = out4 + (size_t)t * TVEC;    // d=0 row
    #pragma unroll
    for (int base = 0; base < ROWVEC; base += 32) {
        int i = base + lane;
        if (i < ROWVEC) o[i] = v4;
    }
}

extern "C" void kernel_launch(void* const* d_in, const int* in_sizes, int n_in,
                              void* d_out, int out_size) {
    const float4* x = (const float4*)d_in[0];  // hidden_state (1, 8192, 400)
    const float4* W = (const float4*)d_in[1];  // W_ap (3, 400)
    const float*  b = (const float*) d_in[2];  // b_ap (3,)
    const float4* D = (const float4*)d_in[3];  // D (1, 400)
    float4* out = (float4*)d_out;              // (1, 8192, 32, 400)

    stackmem_kernel<<<NVBLK + T_LEN, NTHREADS>>>(x, W, b, D, out);
}